// round 1
// baseline (speedup 1.0000x reference)
#include <cuda_runtime.h>

#define N_ROWS 131072
#define ND 13
#define NS 26
#define NF 39
#define EMB 16
#define DDIM 624   // NF*EMB
#define HID 32
#define VOCAB 100000
#define EPSF 1e-5f

#define TILE 32
#define BLK 256
#define GRID_A 148
#define DEEP_STRIDE 628
#define WL1_FLOATS (DDIM*HID)  // 19968
#define SMEM_FLOATS (WL1_FLOATS + TILE*DEEP_STRIDE)
#define SMEM_BYTES (SMEM_FLOATS*4)

// Scratch (device globals: no allocation allowed)
__device__ float g_x1[(size_t)N_ROWS*HID];   // per-row x1 = deep@Wl1 + bl1
__device__ float g_S1[HID];                  // sum x1
__device__ float g_S2[HID*HID];              // sum x1 x1^T
__device__ float g_w[HID];
__device__ float g_C;

__global__ void k_init() {
    int t = threadIdx.x;
    for (int i = t; i < HID*HID; i += blockDim.x) g_S2[i] = 0.f;
    if (t < HID) g_S1[t] = 0.f;
}

__device__ __forceinline__ float hsum4(float4 v){ return v.x+v.y+v.z+v.w; }
__device__ __forceinline__ float4 f4fma(float a, float4 b, float4 c){
    return make_float4(fmaf(a,b.x,c.x), fmaf(a,b.y,c.y), fmaf(a,b.z,c.z), fmaf(a,b.w,c.w));
}
__device__ __forceinline__ float4 f4scale(float4 a, float s){
    return make_float4(a.x*s, a.y*s, a.z*s, a.w*s);
}
__device__ __forceinline__ void f4acc(float4& a, float4 v){
    a.x += v.x; a.y += v.y; a.z += v.z; a.w += v.w;
}

__global__ void __launch_bounds__(BLK,1) k_main(
    const float* __restrict__ Xi_d, const int* __restrict__ Xi_s,
    const float* __restrict__ Xv,   const float* __restrict__ bias,
    const float* __restrict__ W1d,  const float* __restrict__ b1d,
    const float* __restrict__ T1,
    const float* __restrict__ W2d,  const float* __restrict__ b2d,
    const float* __restrict__ T2,
    const float* __restrict__ Wl1,  const float* __restrict__ bl1,
    float* __restrict__ out)
{
    extern __shared__ float smem[];
    float* Wl1s  = smem;               // 19968 floats
    float* deeps = smem + WL1_FLOATS;  // 32 rows * 628 floats

    int tid = threadIdx.x;
    // Stage Wl1 into shared (once per block)
    {
        const float4* src = (const float4*)Wl1;
        float4* dst = (float4*)Wl1s;
        for (int i = tid; i < WL1_FLOATS/4; i += BLK) dst[i] = src[i];
    }
    int lane = tid & 31, wid = tid >> 5;
    float bl1v = bl1[lane];

    float s1p = 0.f;
    float s2p[HID];
    #pragma unroll
    for (int i = 0; i < HID; i++) s2p[i] = 0.f;

    int r   = tid >> 3;   // row within tile (0..31)
    int sub = tid & 7;    // 8 threads cooperate per row

    int ntiles = N_ROWS / TILE;
    for (int tile = blockIdx.x; tile < ntiles; tile += gridDim.x) {
        int row0 = tile * TILE;
        __syncthreads();  // deeps free from previous GEMM reads

        // ---------------- gather / embed phase ----------------
        {
            int row = row0 + r;
            float4 s0={0,0,0,0}, s1={0,0,0,0}, s2={0,0,0,0}, s3={0,0,0,0};
            float sq = 0.f, fst = 0.f;
            float* drow = deeps + r * DEEP_STRIDE;

            #pragma unroll
            for (int k = 0; k < 5; k++) {
                int f = sub + 8*k;
                if (f >= NF) break;
                float xv = Xv[row*NF + f];
                float4 v0, v1, v2, v3;
                float f1sum = 0.f;
                if (f < ND) {
                    float xd = Xi_d[row*ND + f];
                    const float4* w2 = (const float4*)(W2d + f*EMB);
                    const float4* c2 = (const float4*)(b2d + f*EMB);
                    const float4* w1 = (const float4*)(W1d + f*EMB);
                    const float4* c1 = (const float4*)(b1d + f*EMB);
                    v0 = f4scale(f4fma(xd, w2[0], c2[0]), xv);
                    v1 = f4scale(f4fma(xd, w2[1], c2[1]), xv);
                    v2 = f4scale(f4fma(xd, w2[2], c2[2]), xv);
                    v3 = f4scale(f4fma(xd, w2[3], c2[3]), xv);
                    f1sum += hsum4(f4fma(xd, w1[0], c1[0]));
                    f1sum += hsum4(f4fma(xd, w1[1], c1[1]));
                    f1sum += hsum4(f4fma(xd, w1[2], c1[2]));
                    f1sum += hsum4(f4fma(xd, w1[3], c1[3]));
                } else {
                    int sf = f - ND;
                    long base = ((long)sf*VOCAB + Xi_s[row*NS + sf]) * EMB;
                    const float4* t2 = (const float4*)(T2 + base);
                    const float4* t1 = (const float4*)(T1 + base);
                    float4 a0=t2[0], a1=t2[1], a2=t2[2], a3=t2[3];
                    float4 b0=t1[0], b1=t1[1], b2=t1[2], b3=t1[3];
                    v0 = f4scale(a0, xv); v1 = f4scale(a1, xv);
                    v2 = f4scale(a2, xv); v3 = f4scale(a3, xv);
                    f1sum = hsum4(b0)+hsum4(b1)+hsum4(b2)+hsum4(b3);
                }
                fst += xv * f1sum;
                f4acc(s0, v0); f4acc(s1, v1); f4acc(s2, v2); f4acc(s3, v3);
                sq += v0.x*v0.x+v0.y*v0.y+v0.z*v0.z+v0.w*v0.w;
                sq += v1.x*v1.x+v1.y*v1.y+v1.z*v1.z+v1.w*v1.w;
                sq += v2.x*v2.x+v2.y*v2.y+v2.z*v2.z+v2.w*v2.w;
                sq += v3.x*v3.x+v3.y*v3.y+v3.z*v3.z+v3.w*v3.w;
                float4* dstp = (float4*)(drow + f*EMB);
                dstp[0]=v0; dstp[1]=v1; dstp[2]=v2; dstp[3]=v3;
            }
            // reduce across the 8 threads of this row (contiguous lanes)
            #pragma unroll
            for (int off = 4; off; off >>= 1) {
                s0.x += __shfl_down_sync(0xffffffffu, s0.x, off, 8);
                s0.y += __shfl_down_sync(0xffffffffu, s0.y, off, 8);
                s0.z += __shfl_down_sync(0xffffffffu, s0.z, off, 8);
                s0.w += __shfl_down_sync(0xffffffffu, s0.w, off, 8);
                s1.x += __shfl_down_sync(0xffffffffu, s1.x, off, 8);
                s1.y += __shfl_down_sync(0xffffffffu, s1.y, off, 8);
                s1.z += __shfl_down_sync(0xffffffffu, s1.z, off, 8);
                s1.w += __shfl_down_sync(0xffffffffu, s1.w, off, 8);
                s2.x += __shfl_down_sync(0xffffffffu, s2.x, off, 8);
                s2.y += __shfl_down_sync(0xffffffffu, s2.y, off, 8);
                s2.z += __shfl_down_sync(0xffffffffu, s2.z, off, 8);
                s2.w += __shfl_down_sync(0xffffffffu, s2.w, off, 8);
                s3.x += __shfl_down_sync(0xffffffffu, s3.x, off, 8);
                s3.y += __shfl_down_sync(0xffffffffu, s3.y, off, 8);
                s3.z += __shfl_down_sync(0xffffffffu, s3.z, off, 8);
                s3.w += __shfl_down_sync(0xffffffffu, s3.w, off, 8);
                sq  += __shfl_down_sync(0xffffffffu, sq,  off, 8);
                fst += __shfl_down_sync(0xffffffffu, fst, off, 8);
            }
            if (sub == 0) {
                float dots = s0.x*s0.x+s0.y*s0.y+s0.z*s0.z+s0.w*s0.w
                           + s1.x*s1.x+s1.y*s1.y+s1.z*s1.z+s1.w*s1.w
                           + s2.x*s2.x+s2.y*s2.y+s2.z*s2.z+s2.w*s2.w
                           + s3.x*s3.x+s3.y*s3.y+s3.z*s3.z+s3.w*s3.w;
                float fm2 = 0.5f*(dots - sq);
                out[row] = fst + fm2 + bias[row];
            }
        }
        __syncthreads();

        // ---------------- GEMM phase: x1 = deep @ Wl1 + bl1 ----------------
        {
            const float* dp  = deeps + (wid*4) * DEEP_STRIDE;
            const float4* dp0 = (const float4*)(dp);
            const float4* dp1 = (const float4*)(dp +   DEEP_STRIDE);
            const float4* dp2 = (const float4*)(dp + 2*DEEP_STRIDE);
            const float4* dp3 = (const float4*)(dp + 3*DEEP_STRIDE);
            float a0=0.f, a1=0.f, a2=0.f, a3=0.f;
            #pragma unroll 4
            for (int d4 = 0; d4 < DDIM/4; d4++) {
                float4 x0 = dp0[d4], x1v = dp1[d4], x2v = dp2[d4], x3v = dp3[d4];
                const float* wp = Wl1s + d4*4*HID + lane;
                float w0 = wp[0], w1 = wp[HID], w2 = wp[2*HID], w3 = wp[3*HID];
                a0 = fmaf(x0.x,w0,a0); a0 = fmaf(x0.y,w1,a0); a0 = fmaf(x0.z,w2,a0); a0 = fmaf(x0.w,w3,a0);
                a1 = fmaf(x1v.x,w0,a1); a1 = fmaf(x1v.y,w1,a1); a1 = fmaf(x1v.z,w2,a1); a1 = fmaf(x1v.w,w3,a1);
                a2 = fmaf(x2v.x,w0,a2); a2 = fmaf(x2v.y,w1,a2); a2 = fmaf(x2v.z,w2,a2); a2 = fmaf(x2v.w,w3,a2);
                a3 = fmaf(x3v.x,w0,a3); a3 = fmaf(x3v.y,w1,a3); a3 = fmaf(x3v.z,w2,a3); a3 = fmaf(x3v.w,w3,a3);
            }
            float xr0 = a0 + bl1v, xr1 = a1 + bl1v, xr2 = a2 + bl1v, xr3 = a3 + bl1v;
            int rb = row0 + wid*4;
            g_x1[(size_t)(rb+0)*HID + lane] = xr0;
            g_x1[(size_t)(rb+1)*HID + lane] = xr1;
            g_x1[(size_t)(rb+2)*HID + lane] = xr2;
            g_x1[(size_t)(rb+3)*HID + lane] = xr3;
            s1p += xr0 + xr1 + xr2 + xr3;
            #pragma unroll
            for (int i = 0; i < HID; i++) {
                s2p[i] = fmaf(__shfl_sync(0xffffffffu, xr0, i), xr0, s2p[i]);
                s2p[i] = fmaf(__shfl_sync(0xffffffffu, xr1, i), xr1, s2p[i]);
                s2p[i] = fmaf(__shfl_sync(0xffffffffu, xr2, i), xr2, s2p[i]);
                s2p[i] = fmaf(__shfl_sync(0xffffffffu, xr3, i), xr3, s2p[i]);
            }
        }
    }

    // ---------------- block-reduce stats, one atomic per entry ----------------
    __syncthreads();
    float* red = deeps;  // reuse: need 8*1024 + 8*32 floats < 20096
    #pragma unroll
    for (int i = 0; i < HID; i++) red[wid*HID*HID + i*HID + lane] = s2p[i];
    red[8*HID*HID + wid*HID + lane] = s1p;
    __syncthreads();
    for (int k = tid; k < HID*HID; k += BLK) {
        float s = 0.f;
        #pragma unroll
        for (int w = 0; w < 8; w++) s += red[w*HID*HID + k];
        atomicAdd(&g_S2[k], s);
    }
    if (tid < HID) {
        float s = 0.f;
        #pragma unroll
        for (int w = 0; w < 8; w++) s += red[8*HID*HID + w*HID + tid];
        atomicAdd(&g_S1[tid], s);
    }
}

// Collapse BN->Linear->BN->rowsum into w (32) and scalar C, in fp64.
__global__ void k_stats(const float* __restrict__ Wl2, const float* __restrict__ bl2,
                        const float* __restrict__ g1,  const float* __restrict__ be1,
                        const float* __restrict__ g2,  const float* __restrict__ be2)
{
    __shared__ double m1s[HID], als[HID], bes[HID], ts[HID], cred[HID];
    __shared__ double Cov[HID][HID];
    int i = threadIdx.x;  // 32 threads
    const double invN = 1.0 / (double)N_ROWS;

    double m1 = (double)g_S1[i] * invN;
    m1s[i] = m1;
    __syncwarp();
    for (int k = 0; k < HID; k++)
        Cov[i][k] = (double)g_S2[i*HID + k] * invN - m1 * m1s[k];
    double v1 = Cov[i][i];
    double al = (double)g1[i] / sqrt(v1 + (double)EPSF);
    double be = (double)be1[i] - al * m1;
    als[i] = al; bes[i] = be;
    __syncwarp();

    int j = i;
    double cj = (double)bl2[j];
    double m2o = 0.0;
    for (int k = 0; k < HID; k++) {
        double wkj = (double)Wl2[k*HID + j];
        cj  += bes[k] * wkj;
        m2o += als[k] * wkj * m1s[k];
    }
    double v2 = 0.0;
    for (int a = 0; a < HID; a++) {
        double Ma = als[a] * (double)Wl2[a*HID + j];
        double acc = 0.0;
        for (int b = 0; b < HID; b++)
            acc += Cov[a][b] * (als[b] * (double)Wl2[b*HID + j]);
        v2 += Ma * acc;
    }
    double tj = (double)g2[j] / sqrt(v2 + (double)EPSF);
    ts[j] = tj;
    cred[j] = -tj * m2o + (double)be2[j];
    __syncwarp();

    double wsum = 0.0;
    for (int j2 = 0; j2 < HID; j2++) wsum += (double)Wl2[i*HID + j2] * ts[j2];
    g_w[i] = (float)(als[i] * wsum);

    double c = cred[i];
    #pragma unroll
    for (int off = 16; off; off >>= 1) c += __shfl_down_sync(0xffffffffu, c, off);
    if (i == 0) g_C = (float)c;
}

__global__ void k_final(float* __restrict__ out) {
    __shared__ float ws[HID];
    __shared__ float Cs;
    if (threadIdx.x < HID) ws[threadIdx.x] = g_w[threadIdx.x];
    if (threadIdx.x == 0)  Cs = g_C;
    __syncthreads();
    int row = blockIdx.x * blockDim.x + threadIdx.x;  // grid sized exactly N
    const float4* xp  = (const float4*)(g_x1 + (size_t)row * HID);
    const float4* wp4 = (const float4*)ws;
    float acc = Cs;
    #pragma unroll
    for (int q = 0; q < 8; q++) {
        float4 x = xp[q], w = wp4[q];
        acc += x.x*w.x + x.y*w.y + x.z*w.z + x.w*w.w;
    }
    out[row] += acc;
}

extern "C" void kernel_launch(void* const* d_in, const int* in_sizes, int n_in,
                              void* d_out, int out_size)
{
    const float* Xi_d = (const float*)d_in[0];
    const int*   Xi_s = (const int*)  d_in[1];
    const float* Xv   = (const float*)d_in[2];
    const float* bias = (const float*)d_in[3];
    const float* W1d  = (const float*)d_in[4];
    const float* b1d  = (const float*)d_in[5];
    const float* T1   = (const float*)d_in[6];
    const float* W2d  = (const float*)d_in[7];
    const float* b2d  = (const float*)d_in[8];
    const float* T2   = (const float*)d_in[9];
    const float* Wl1  = (const float*)d_in[10];
    const float* bl1  = (const float*)d_in[11];
    const float* g1   = (const float*)d_in[12];
    const float* be1  = (const float*)d_in[13];
    const float* Wl2  = (const float*)d_in[14];
    const float* bl2  = (const float*)d_in[15];
    const float* g2   = (const float*)d_in[16];
    const float* be2  = (const float*)d_in[17];
    float* out = (float*)d_out;

    cudaFuncSetAttribute(k_main, cudaFuncAttributeMaxDynamicSharedMemorySize, SMEM_BYTES);

    k_init<<<1, 256>>>();
    k_main<<<GRID_A, BLK, SMEM_BYTES>>>(Xi_d, Xi_s, Xv, bias,
                                        W1d, b1d, T1, W2d, b2d, T2,
                                        Wl1, bl1, out);
    k_stats<<<1, 32>>>(Wl2, bl2, g1, be1, g2, be2);
    k_final<<<N_ROWS/256, 256>>>(out);
}